// round 3
// baseline (speedup 1.0000x reference)
#include <cuda_runtime.h>
#include <math.h>
#define NN 512
#define KK 50

__device__ float g_a[2*KK*NN], g_c[2*NN*KK], g_oa[2*NN*32], g_ob[2*NN*32];

__device__ __forceinline__ float silu(float v){return v/(1.f+__expf(-v));}

__global__ void pre_node(const float* __restrict__ h,const float* __restrict__ W_in,
                         const float* __restrict__ b_in,const float* __restrict__ W_o1){
  int bn=blockIdx.x,b=bn>>9,n=bn&(NN-1),t=threadIdx.x;
  __shared__ float hr[32];
  if(t<32)hr[t]=h[bn*32+t];
  __syncthreads();
  if(t<KK){
    float a=0,c=b_in[t];
    for(int f=0;f<32;f++){a=fmaf(hr[f],W_in[f*KK+t],a);c=fmaf(hr[f],W_in[(32+f)*KK+t],c);}
    g_a[((b*KK+t)<<9)+n]=a; g_c[bn*KK+t]=c;
  }else if(t>=64&&t<96){
    int q=t-64;float a=0;
    for(int f=0;f<32;f++)a=fmaf(hr[f],W_o1[f*32+q],a);
    g_oa[(bn<<5)+q]=a;
  }else if(t>=96&&t<128){
    int q=t-96;float a=0;
    for(int f=0;f<32;f++)a=fmaf(hr[f],W_o1[(32+f)*32+q],a);
    g_ob[(bn<<5)+q]=a;
  }
}

// smem offsets (floats)
#define O_HE 0
#define O_UN 18432
#define O_WM 20480
#define O_WO2 22112
#define O_WS 23136
#define O_MB 23264
#define O_BB 23314
#define O_CI 23364
#define O_B1 23414
#define O_B2 23446
#define O_OB 23478
#define O_HI 23510
#define O_BS 23542
#define O_GM 23546
#define O_XI 23550
#define O_VI 23554
#define O_RD 23558
#define O_CS 23590
#define O_HA 23974
#define O_HC 24102
#define O_T1 24134
#define O_T2 24166
#define O_T3 24198
#define O_SC 24230
#define SMF 24240
#define O_PT O_WM
#define O_HCI (O_WM+1024)
#define O_IN (O_WM+1200)

__device__ __forceinline__ void bred4(float* v,int mx,float* sm){
  for(int s2=16;s2;s2>>=1)
    for(int hd=0;hd<4;hd++){float o=__shfl_xor_sync(~0u,v[hd],s2);v[hd]=mx?fmaxf(v[hd],o):v[hd]+o;}
  __syncthreads();
  if((threadIdx.x&31)==0)for(int hd=0;hd<4;hd++)sm[O_RD+(threadIdx.x>>5)*4+hd]=v[hd];
  __syncthreads();
  for(int hd=0;hd<4;hd++){float r=sm[O_RD+hd];
    for(int w=1;w<8;w++){float o=sm[O_RD+w*4+hd];r=mx?fmaxf(r,o):r+o;}v[hd]=r;}
  __syncthreads();
}

__device__ __forceinline__ void gmv(const float* in,int n,const float* W,const float* bb,float* o,int t){
  if(t<128){
    int oh=t>>2,pr=t&3,ch=n>>2;float v=0;
    for(int ii=pr*ch;ii<pr*ch+ch;ii++)v=fmaf(in[ii],__ldg(W+ii*32+oh),v);
    v+=__shfl_xor_sync(~0u,v,1);v+=__shfl_xor_sync(~0u,v,2);
    if(pr==0)o[oh]=silu(v+__ldg(bb+oh));
  }
  __syncthreads();
}

__global__ __launch_bounds__(256,2) void sake_main(
  const float* __restrict__ h,const float* __restrict__ x,const float* __restrict__ v,
  const float* __restrict__ means,const float* __restrict__ betas,
  const float* __restrict__ W_o1,const float* __restrict__ b_o1,
  const float* __restrict__ W_o2,const float* __restrict__ b_o2,
  const float* __restrict__ W_sem,const float* __restrict__ b_sem,
  const float* __restrict__ W_pn1,const float* __restrict__ b_pn1,
  const float* __restrict__ W_pn2,const float* __restrict__ b_pn2,
  const float* __restrict__ W_n1,const float* __restrict__ b_n1,
  const float* __restrict__ W_n2,const float* __restrict__ b_n2,
  const float* __restrict__ W_v1,const float* __restrict__ b_v1,
  const float* __restrict__ W_v2,const float* __restrict__ W_vm,
  const float* __restrict__ log_gamma,float* __restrict__ out){
  extern __shared__ float sm[];
  const int b=blockIdx.x>>9,i=blockIdx.x&(NN-1),t=threadIdx.x;

  for(int q=t;q<1632;q+=256)sm[O_WM+q]=W_o1[64*32+q];
  for(int q=t;q<1024;q+=256)sm[O_WO2+q]=W_o2[q];
  if(t<128)sm[O_WS+t]=W_sem[t];
  if(t<KK){sm[O_MB+t]=means[t];sm[O_BB+t]=betas[t];sm[O_CI+t]=g_c[(b*NN+i)*KK+t];}
  if(t<32){sm[O_B1+t]=b_o1[t];sm[O_B2+t]=b_o2[t];
    sm[O_OB+t]=g_ob[((b*NN+i)<<5)+t];sm[O_HI+t]=h[(b*NN+i)*32+t];}
  if(t<4){sm[O_BS+t]=b_sem[t];sm[O_GM+t]=__expf(log_gamma[t]);}
  if(t>=4&&t<7){sm[O_XI+t-4]=x[(b*NN+i)*3+t-4];sm[O_VI+t-4]=v[(b*NN+i)*3+t-4];}
  __syncthreads();

  // phase A: edge model per pair
  for(int jr=0;jr<2;jr++){
    int j=t+(jr<<8);
    const float* xb=x+(size_t)(b*NN+j)*3;
    float d0=xb[0]-sm[O_XI],d1=xb[1]-sm[O_XI+1],d2=xb[2]-sm[O_XI+2];
    float nr=sqrtf(d0*d0+d1*d1+d2*d2+1e-5f),ri=1.f/(nr+1e-5f);
    *(float4*)&sm[O_UN+j*4]=make_float4(d0*ri,d1*ri,d2*ri,nr);
    float e=__expf(-nr);
    float cut=(nr<5.f)?0.5f*(__cosf(nr*0.6283185307179586f)+1.f):0.f;
    float acc[32];
    const float* oa=g_oa+((size_t)(b*NN+j)<<5);
    #pragma unroll
    for(int q=0;q<32;q++)acc[q]=oa[q]+sm[O_OB+q]+nr*sm[O_WM+1600+q]+sm[O_B1+q];
    const float* ga=g_a+(((size_t)b*KK)<<9)+j;
    for(int k=0;k<KK;k++){
      float dm=e-sm[O_MB+k];
      float w=cut*__expf(-sm[O_BB+k]*dm*dm)*(ga[(size_t)k<<9]+sm[O_CI+k]);
      const float4* wr=(const float4*)&sm[O_WM+k*32];
      #pragma unroll
      for(int q=0;q<8;q++){float4 wv=wr[q];
        acc[4*q]+=w*wv.x;acc[4*q+1]+=w*wv.y;acc[4*q+2]+=w*wv.z;acc[4*q+3]+=w*wv.w;}
    }
    float s[32];
    #pragma unroll
    for(int q=0;q<32;q++)s[q]=silu(acc[q]);
    #pragma unroll
    for(int q=0;q<32;q++)acc[q]=sm[O_B2+q];
    #pragma unroll
    for(int o=0;o<32;o++){
      float sv=s[o];const float4* wr=(const float4*)&sm[O_WO2+o*32];
      #pragma unroll
      for(int q=0;q<8;q++){float4 wv=wr[q];
        acc[4*q]+=sv*wv.x;acc[4*q+1]+=sv*wv.y;acc[4*q+2]+=sv*wv.z;acc[4*q+3]+=sv*wv.w;}
    }
    float4* her=(float4*)&sm[O_HE+j*36];
    float sl[4]={sm[O_BS],sm[O_BS+1],sm[O_BS+2],sm[O_BS+3]};
    #pragma unroll
    for(int q=0;q<32;q++){
      float4 wv=*(const float4*)&sm[O_WS+q*4];
      sl[0]+=acc[q]*wv.x;sl[1]+=acc[q]*wv.y;sl[2]+=acc[q]*wv.z;sl[3]+=acc[q]*wv.w;
    }
    #pragma unroll
    for(int q=0;q<8;q++)her[q]=make_float4(acc[4*q],acc[4*q+1],acc[4*q+2],acc[4*q+3]);
    her[8]=make_float4(sl[0],sl[1],sl[2],sl[3]);
  }
  __syncthreads();

  // softmaxes over j (j0=t, j1=t+256)
  {
    int j0=t,j1=t+256;
    float nr0=sm[O_UN+j0*4+3],nr1=sm[O_UN+j1*4+3];
    float mk0=(j0==i)?1e5f:0.f,mk1=(j1==i)?1e5f:0.f;
    float4 q0=*(float4*)&sm[O_HE+j0*36+32],q1=*(float4*)&sm[O_HE+j1*36+32];
    float s0[4]={q0.x,q0.y,q0.z,q0.w},s1[4]={q1.x,q1.y,q1.z,q1.w};
    float e0[4],e1[4],r[4];
    for(int hd=0;hd<4;hd++){
      float g=sm[O_GM+hd];
      e0[hd]=-(nr0+mk0)*g;e1[hd]=-(nr1+mk1)*g;r[hd]=fmaxf(e0[hd],e1[hd]);
    }
    bred4(r,1,sm);
    for(int hd=0;hd<4;hd++){e0[hd]=__expf(e0[hd]-r[hd]);e1[hd]=__expf(e1[hd]-r[hd]);r[hd]=e0[hd]+e1[hd];}
    bred4(r,0,sm);
    for(int hd=0;hd<4;hd++){float iv=1.f/r[hd];e0[hd]*=iv;e1[hd]*=iv;}
    for(int hd=0;hd<4;hd++){
      float a=s0[hd];a=(a>0.f)?a:0.2f*a;s0[hd]=a-mk0;
      float c=s1[hd];c=(c>0.f)?c:0.2f*c;s1[hd]=c-mk1;
      r[hd]=fmaxf(s0[hd],s1[hd]);
    }
    bred4(r,1,sm);
    for(int hd=0;hd<4;hd++){s0[hd]=__expf(s0[hd]-r[hd]);s1[hd]=__expf(s1[hd]-r[hd]);r[hd]=s0[hd]+s1[hd];}
    bred4(r,0,sm);
    for(int hd=0;hd<4;hd++){float iv=1.f/r[hd];s0[hd]*=iv;s1[hd]*=iv;}
    float c0[4],c1[4];
    for(int hd=0;hd<4;hd++){c0[hd]=__expf(e0[hd]*s0[hd]);c1[hd]=__expf(e1[hd]*s1[hd]);r[hd]=c0[hd]+c1[hd];}
    bred4(r,0,sm);
    for(int hd=0;hd<4;hd++){float iv=1.f/r[hd];c0[hd]*=iv;c1[hd]*=iv;}
    *(float4*)&sm[O_HE+j0*36+32]=make_float4(c0[0],c0[1],c0[2],c0[3]);
    *(float4*)&sm[O_HE+j1*36+32]=make_float4(c1[0],c1[1],c1[2],c1[3]);
  }
  __syncthreads();

  // phase C: per (c,half) reductions over j
  {
    int c=t&127,half=t>>7,hid=c>>2,hd=c&3;
    float a0=0,a1=0,a2=0,a3=0;
    int jb=half<<8;
    for(int j=jb;j<jb+256;j++){
      float p=sm[O_HE+j*36+hid]*sm[O_HE+j*36+32+hd];
      float4 u=*(float4*)&sm[O_UN+j*4];
      a0+=p;a1+=p*u.x;a2+=p*u.y;a3+=p*u.z;
    }
    __syncthreads();
    float* pt=&sm[O_PT+c*8+half*4];
    pt[0]=a0;pt[1]=a1;pt[2]=a2;pt[3]=a3;
  }
  __syncthreads();
  for(int r2=0;r2<2;r2++){
    int q=t+(r2<<8),c=q>>2,m=q&3;
    float vv=sm[O_PT+c*8+m]+sm[O_PT+c*8+4+m];
    if(m==0)sm[O_HA+c]=vv;else sm[O_CS+c*3+m-1]=vv*(1.f/512.f);
  }
  __syncthreads();

  // epilogue
  if(t<128){
    float c0=sm[O_CS+t*3],c1=sm[O_CS+t*3+1],c2=sm[O_CS+t*3+2];
    sm[O_HCI+t]=c0*c0+c1*c1+c2*c2;
  }
  __syncthreads();
  gmv(&sm[O_HCI],128,W_pn1,b_pn1,&sm[O_T1],t);
  gmv(&sm[O_T1],32,W_pn2,b_pn2,&sm[O_HC],t);
  if(t<192)sm[O_IN+t]=(t<32)?sm[O_HI+t]:(t<160)?sm[O_HA+t-32]:sm[O_HC+t-160];
  __syncthreads();
  gmv(&sm[O_IN],192,W_n1,b_n1,&sm[O_T1],t);
  if(t<128){
    int oh=t>>2,pr=t&3;float vv=0;
    for(int ii=pr*8;ii<pr*8+8;ii++)vv=fmaf(sm[O_T1+ii],__ldg(W_n2+ii*32+oh),vv);
    vv+=__shfl_xor_sync(~0u,vv,1);vv+=__shfl_xor_sync(~0u,vv,2);
    if(pr==0){
      float hv=sm[O_HI+oh]+silu(vv+__ldg(b_n2+oh));
      sm[O_T2+oh]=hv;
      out[(b*NN+i)*32+oh]=hv;
    }
  }
  __syncthreads();
  gmv(&sm[O_T2],32,W_v1,b_v1,&sm[O_T3],t);
  if(t<32){
    float g=sm[O_T3+t]*__ldg(W_v2+t);
    for(int s2=16;s2;s2>>=1)g+=__shfl_xor_sync(~0u,g,s2);
    if(t==0)sm[O_SC]=g;
  }
  if(t>=32&&t<128){
    int d=(t>>5)-1,ln=t&31;float vv=0;
    for(int r2=0;r2<4;r2++){int c=ln+(r2<<5);vv=fmaf(sm[O_CS+c*3+d],__ldg(W_vm+c),vv);}
    for(int s2=16;s2;s2>>=1)vv+=__shfl_xor_sync(~0u,vv,s2);
    if(ln==0)sm[O_SC+1+d]=vv;
  }
  __syncthreads();
  if(t<3){
    float vn=sm[O_SC]*sm[O_VI+t]+sm[O_SC+1+t];
    out[32768+(b*NN+i)*3+t]=sm[O_XI+t]+vn;
    out[35840+(b*NN+i)*3+t]=vn;
  }
}

extern "C" void kernel_launch(void* const* d_in,const int* in_sizes,int n_in,
                              void* d_out,int out_size){
  const float *h=(const float*)d_in[0],*x=(const float*)d_in[1],*v=(const float*)d_in[2],
    *means=(const float*)d_in[3],*betas=(const float*)d_in[4],
    *W_in=(const float*)d_in[5],*b_in=(const float*)d_in[6],
    *W_o1=(const float*)d_in[7],*b_o1=(const float*)d_in[8],
    *W_o2=(const float*)d_in[9],*b_o2=(const float*)d_in[10],
    *W_sem=(const float*)d_in[11],*b_sem=(const float*)d_in[12],
    *W_pn1=(const float*)d_in[13],*b_pn1=(const float*)d_in[14],
    *W_pn2=(const float*)d_in[15],*b_pn2=(const float*)d_in[16],
    *W_n1=(const float*)d_in[17],*b_n1=(const float*)d_in[18],
    *W_n2=(const float*)d_in[19],*b_n2=(const float*)d_in[20],
    *W_v1=(const float*)d_in[21],*b_v1=(const float*)d_in[22],
    *W_v2=(const float*)d_in[23],*W_vm=(const float*)d_in[24],
    *log_gamma=(const float*)d_in[25];
  float* out=(float*)d_out;
  cudaFuncSetAttribute(sake_main,cudaFuncAttributeMaxDynamicSharedMemorySize,SMF*4);
  pre_node<<<1024,128>>>(h,W_in,b_in,W_o1);
  sake_main<<<1024,256,SMF*4>>>(h,x,v,means,betas,W_o1,b_o1,W_o2,b_o2,W_sem,b_sem,
    W_pn1,b_pn1,W_pn2,b_pn2,W_n1,b_n1,W_n2,b_n2,W_v1,b_v1,W_v2,W_vm,log_gamma,out);
}

// round 4
// speedup vs baseline: 1.0293x; 1.0293x over previous
#include <cuda_runtime.h>
#include <math.h>
#define NN 512
#define KK 50

__device__ float g_a[2*KK*NN], g_c[2*NN*KK], g_oa[2*32*NN], g_ob[2*NN*32];
__device__ float g_wos[128], g_bos[4];

__device__ __forceinline__ float silu(float v){return v/(1.f+__expf(-v));}
__device__ __forceinline__ unsigned long long pk(float a,float b){
  unsigned long long r;asm("mov.b64 %0,{%1,%2};":"=l"(r):"f"(a),"f"(b));return r;}
__device__ __forceinline__ void upk(unsigned long long p,float&a,float&b){
  asm("mov.b64 {%0,%1},%2;":"=f"(a),"=f"(b):"l"(p));}
__device__ __forceinline__ void fma2(unsigned long long&d,unsigned long long a,unsigned long long b){
  asm("fma.rn.f32x2 %0,%1,%2,%0;":"+l"(d):"l"(a),"l"(b));}
__device__ __forceinline__ void lds2(unsigned a,unsigned long long&x,unsigned long long&y){
  asm("ld.shared.v2.b64 {%0,%1},[%2];":"=l"(x),"=l"(y):"r"(a));}

__global__ void pre_wos(const float* __restrict__ W_o2,const float* __restrict__ W_sem,
                        const float* __restrict__ b_o2,const float* __restrict__ b_sem){
  int t=threadIdx.x;
  if(t<128){int o=t>>2,hd=t&3;float a=0;
    for(int m=0;m<32;m++)a=fmaf(W_o2[o*32+m],W_sem[m*4+hd],a);
    g_wos[t]=a;
  }else if(t<132){int hd=t-128;float a=b_sem[hd];
    for(int m=0;m<32;m++)a=fmaf(b_o2[m],W_sem[m*4+hd],a);
    g_bos[hd]=a;}
}

__global__ void pre_node(const float* __restrict__ h,const float* __restrict__ W_in,
                         const float* __restrict__ b_in,const float* __restrict__ W_o1){
  int bn=blockIdx.x,b=bn>>9,n=bn&(NN-1),t=threadIdx.x;
  __shared__ float hr[32];
  if(t<32)hr[t]=h[bn*32+t];
  __syncthreads();
  if(t<KK){
    float a=0,c=b_in[t];
    for(int f=0;f<32;f++){a=fmaf(hr[f],W_in[f*KK+t],a);c=fmaf(hr[f],W_in[(32+f)*KK+t],c);}
    g_a[((b*KK+t)<<9)+n]=a; g_c[bn*KK+t]=c;
  }else if(t>=64&&t<96){
    int q=t-64;float a=0;
    for(int f=0;f<32;f++)a=fmaf(hr[f],W_o1[f*32+q],a);
    g_oa[((b*32+q)<<9)+n]=a;
  }else if(t>=96&&t<128){
    int q=t-96;float a=0;
    for(int f=0;f<32;f++)a=fmaf(hr[f],W_o1[(32+f)*32+q],a);
    g_ob[(bn<<5)+q]=a;
  }
}

// smem float offsets
#define O_S   0        // 512*40: s[32], sem/comb[4], unit[3]+nrm
#define O_WM  20480    // 1632 W_o1 rows 64..114 ; W_o2(1024) overlay after phase A
#define O_MBC 22112    // 50*4
#define O_WOS 22312    // 128
#define O_BOS 22440
#define O_B1  22444
#define O_B2  22476
#define O_OB  22508
#define O_HI  22540
#define O_GM  22572
#define O_XI  22576
#define O_VI  22580
#define O_RD  22584    // 32
#define O_U   22616    // 12
#define O_PT  22628    // 4096
#define SMF   26724
#define O_T   O_PT
#define O_HE  (O_PT+512)
#define O_CS  (O_PT+640)
#define O_HCI (O_PT+1024)
#define O_T1  (O_PT+1152)
#define O_T2  (O_PT+1184)
#define O_T3  (O_PT+1216)
#define O_SC  (O_PT+1248)

__device__ __forceinline__ void bred4(float* v,int mx,float* sm){
  for(int s2=16;s2;s2>>=1)
    for(int hd=0;hd<4;hd++){float o=__shfl_xor_sync(~0u,v[hd],s2);v[hd]=mx?fmaxf(v[hd],o):v[hd]+o;}
  __syncthreads();
  if((threadIdx.x&31)==0)for(int hd=0;hd<4;hd++)sm[O_RD+(threadIdx.x>>5)*4+hd]=v[hd];
  __syncthreads();
  for(int hd=0;hd<4;hd++){float r=sm[O_RD+hd];
    for(int w=1;w<8;w++){float o=sm[O_RD+w*4+hd];r=mx?fmaxf(r,o):r+o;}v[hd]=r;}
  __syncthreads();
}

__device__ __forceinline__ void gmv(const float* in,int n,const float* W,const float* bb,float* o,int t){
  if(t<128){
    int oh=t>>2,pr=t&3,ch=n>>2;float v=0;
    for(int ii=pr*ch;ii<pr*ch+ch;ii++)v=fmaf(in[ii],__ldg(W+ii*32+oh),v);
    v+=__shfl_xor_sync(~0u,v,1);v+=__shfl_xor_sync(~0u,v,2);
    if(pr==0)o[oh]=silu(v+__ldg(bb+oh));
  }
  __syncthreads();
}

__global__ __launch_bounds__(256,2) void sake_main(
  const float* __restrict__ h,const float* __restrict__ x,const float* __restrict__ v,
  const float* __restrict__ means,const float* __restrict__ betas,
  const float* __restrict__ W_o1,const float* __restrict__ b_o1,
  const float* __restrict__ W_o2,const float* __restrict__ b_o2,
  const float* __restrict__ W_pn1,const float* __restrict__ b_pn1,
  const float* __restrict__ W_pn2,const float* __restrict__ b_pn2,
  const float* __restrict__ W_n1,const float* __restrict__ b_n1,
  const float* __restrict__ W_n2,const float* __restrict__ b_n2,
  const float* __restrict__ W_v1,const float* __restrict__ b_v1,
  const float* __restrict__ W_v2,const float* __restrict__ W_vm,
  const float* __restrict__ log_gamma,float* __restrict__ out){
  extern __shared__ float sm[];
  const int b=blockIdx.x>>9,i=blockIdx.x&(NN-1),t=threadIdx.x;
  const unsigned su=(unsigned)__cvta_generic_to_shared(sm);

  for(int q=t;q<1632;q+=256)sm[O_WM+q]=W_o1[64*32+q];
  if(t<128)sm[O_WOS+t]=g_wos[t];
  if(t<KK)*(float4*)&sm[O_MBC+t*4]=make_float4(means[t],betas[t],g_c[(b*NN+i)*KK+t],0.f);
  if(t>=64&&t<96){int q=t-64;sm[O_B1+q]=b_o1[q];sm[O_B2+q]=b_o2[q];}
  if(t>=96&&t<128){int q=t-96;sm[O_OB+q]=g_ob[((b*NN+i)<<5)+q];sm[O_HI+q]=h[(b*NN+i)*32+q];}
  if(t>=128&&t<132){sm[O_BOS+t-128]=g_bos[t-128];sm[O_GM+t-128]=__expf(log_gamma[t-128]);}
  if(t>=132&&t<135){sm[O_XI+t-132]=x[(b*NN+i)*3+t-132];sm[O_VI+t-132]=v[(b*NN+i)*3+t-132];}
  __syncthreads();

  // phase A: edge model; store s, sem logits, unit+nrm
  #pragma unroll 1
  for(int jr=0;jr<2;jr++){
    int j=t+(jr<<8);
    const float* xb=x+(size_t)((b<<9)+j)*3;
    float d0=xb[0]-sm[O_XI],d1=xb[1]-sm[O_XI+1],d2=xb[2]-sm[O_XI+2];
    float nr=sqrtf(d0*d0+d1*d1+d2*d2+1e-5f),ri=1.f/(nr+1e-5f);
    *(float4*)&sm[O_S+j*40+36]=make_float4(d0*ri,d1*ri,d2*ri,nr);
    float e=__expf(-nr);
    float cut=(nr<5.f)?0.5f*(__cosf(nr*0.6283185307179586f)+1.f):0.f;
    unsigned long long acc[16];
    const float* oa=g_oa+(((size_t)b*32)<<9)+j;
    #pragma unroll
    for(int q=0;q<16;q++){
      float a0=oa[(size_t)(2*q)<<9],a1=oa[(size_t)(2*q+1)<<9];
      acc[q]=pk(a0+sm[O_OB+2*q]+nr*sm[O_WM+1600+2*q]+sm[O_B1+2*q],
                a1+sm[O_OB+2*q+1]+nr*sm[O_WM+1600+2*q+1]+sm[O_B1+2*q+1]);
    }
    const float* ga=g_a+(((size_t)b*KK)<<9)+j;
    #pragma unroll 2
    for(int k=0;k<KK;k++){
      float4 mbc=*(float4*)&sm[O_MBC+k*4];
      float dm=e-mbc.x;
      float w=cut*__expf(-mbc.y*dm*dm)*(ga[(size_t)k<<9]+mbc.z);
      unsigned long long wp=pk(w,w);
      unsigned wa=su+(unsigned)((O_WM+k*32)*4);
      #pragma unroll
      for(int q=0;q<8;q++){
        unsigned long long w0,w1;lds2(wa+q*16,w0,w1);
        fma2(acc[2*q],wp,w0);fma2(acc[2*q+1],wp,w1);
      }
    }
    float s[32];
    #pragma unroll
    for(int q=0;q<16;q++){float a,bb;upk(acc[q],a,bb);s[2*q]=silu(a);s[2*q+1]=silu(bb);}
    #pragma unroll
    for(int q=0;q<8;q++)*(float4*)&sm[O_S+j*40+q*4]=make_float4(s[4*q],s[4*q+1],s[4*q+2],s[4*q+3]);
    unsigned long long a01=pk(sm[O_BOS],sm[O_BOS+1]),a23=pk(sm[O_BOS+2],sm[O_BOS+3]);
    #pragma unroll
    for(int q=0;q<32;q++){
      unsigned long long w0,w1;lds2(su+(unsigned)((O_WOS+q*4)*4),w0,w1);
      unsigned long long sp=pk(s[q],s[q]);
      fma2(a01,sp,w0);fma2(a23,sp,w1);
    }
    float l0,l1,l2,l3;upk(a01,l0,l1);upk(a23,l2,l3);
    *(float4*)&sm[O_S+j*40+32]=make_float4(l0,l1,l2,l3);
  }
  __syncthreads();
  for(int q=t;q<1024;q+=256)sm[O_WM+q]=W_o2[q];  // overlay

  // softmaxes
  float c0[4],c1[4];
  {
    int j0=t,j1=t+256;
    float nr0=sm[O_S+j0*40+39],nr1=sm[O_S+j1*40+39];
    float mk0=(j0==i)?1e5f:0.f,mk1=(j1==i)?1e5f:0.f;
    float4 q0=*(float4*)&sm[O_S+j0*40+32],q1=*(float4*)&sm[O_S+j1*40+32];
    float s0[4]={q0.x,q0.y,q0.z,q0.w},s1[4]={q1.x,q1.y,q1.z,q1.w};
    float e0[4],e1[4],r[4];
    for(int hd=0;hd<4;hd++){float g=sm[O_GM+hd];
      e0[hd]=-(nr0+mk0)*g;e1[hd]=-(nr1+mk1)*g;r[hd]=fmaxf(e0[hd],e1[hd]);}
    bred4(r,1,sm);
    for(int hd=0;hd<4;hd++){e0[hd]=__expf(e0[hd]-r[hd]);e1[hd]=__expf(e1[hd]-r[hd]);r[hd]=e0[hd]+e1[hd];}
    bred4(r,0,sm);
    for(int hd=0;hd<4;hd++){float iv=1.f/r[hd];e0[hd]*=iv;e1[hd]*=iv;}
    for(int hd=0;hd<4;hd++){
      float a=s0[hd];a=(a>0.f)?a:0.2f*a;s0[hd]=a-mk0;
      float c=s1[hd];c=(c>0.f)?c:0.2f*c;s1[hd]=c-mk1;
      r[hd]=fmaxf(s0[hd],s1[hd]);}
    bred4(r,1,sm);
    for(int hd=0;hd<4;hd++){s0[hd]=__expf(s0[hd]-r[hd]);s1[hd]=__expf(s1[hd]-r[hd]);r[hd]=s0[hd]+s1[hd];}
    bred4(r,0,sm);
    for(int hd=0;hd<4;hd++){float iv=1.f/r[hd];s0[hd]*=iv;s1[hd]*=iv;}
    for(int hd=0;hd<4;hd++){c0[hd]=__expf(e0[hd]*s0[hd]);c1[hd]=__expf(e1[hd]*s1[hd]);r[hd]=c0[hd]+c1[hd];}
    bred4(r,0,sm);
    for(int hd=0;hd<4;hd++){float iv=1.f/r[hd];c0[hd]*=iv;c1[hd]*=iv;}
    *(float4*)&sm[O_S+j0*40+32]=make_float4(c0[0],c0[1],c0[2],c0[3]);
    *(float4*)&sm[O_S+j1*40+32]=make_float4(c1[0],c1[1],c1[2],c1[3]);
    // U[hd][d] = sum_j comb*unit
    float4 un0=*(float4*)&sm[O_S+j0*40+36],un1=*(float4*)&sm[O_S+j1*40+36];
    float ua[3]={un0.x,un0.y,un0.z},ub[3]={un1.x,un1.y,un1.z};
    for(int d=0;d<3;d++){
      for(int hd=0;hd<4;hd++)r[hd]=c0[hd]*ua[d]+c1[hd]*ub[d];
      bred4(r,0,sm);
      if(t==0)for(int hd=0;hd<4;hd++)sm[O_U+hd*3+d]=r[hd];
    }
  }

  // phase C: T[o,hd,m] partials (f32x2)
  {
    int lane=t&31,slice=t>>5,og=lane>>2,hd=lane&3;
    unsigned long long ac[4][2];
    #pragma unroll
    for(int c=0;c<4;c++){ac[c][0]=0ull;ac[c][1]=0ull;}
    int jb=slice<<6;
    for(int jj=0;jj<64;jj++){
      int row=O_S+(jb+jj)*40;
      float4 s4=*(float4*)&sm[row+og*4];
      float cb=sm[row+32+hd];
      float4 un=*(float4*)&sm[row+36];
      unsigned long long q01=pk(1.f,un.x),q23=pk(un.y,un.z),p;
      p=pk(s4.x*cb,s4.x*cb);fma2(ac[0][0],p,q01);fma2(ac[0][1],p,q23);
      p=pk(s4.y*cb,s4.y*cb);fma2(ac[1][0],p,q01);fma2(ac[1][1],p,q23);
      p=pk(s4.z*cb,s4.z*cb);fma2(ac[2][0],p,q01);fma2(ac[2][1],p,q23);
      p=pk(s4.w*cb,s4.w*cb);fma2(ac[3][0],p,q01);fma2(ac[3][1],p,q23);
    }
    #pragma unroll
    for(int c=0;c<4;c++){
      float v0,v1,v2,v3;upk(ac[c][0],v0,v1);upk(ac[c][1],v2,v3);
      int ix=c*4;
      sm[O_PT+lane+32*((ix+0)*8+slice)]=v0;
      sm[O_PT+lane+32*((ix+1)*8+slice)]=v1;
      sm[O_PT+lane+32*((ix+2)*8+slice)]=v2;
      sm[O_PT+lane+32*((ix+3)*8+slice)]=v3;
    }
  }
  __syncthreads();
  float vv0=0,vv1=0;
  {
    int combo=t&31,i0=t>>5,i1=(t>>5)+8;
    #pragma unroll
    for(int s2=0;s2<8;s2++){
      vv0+=sm[O_PT+combo+32*(i0*8+s2)];
      vv1+=sm[O_PT+combo+32*(i1*8+s2)];
    }
  }
  __syncthreads();
  sm[O_T+(t&31)+32*(t>>5)]=vv0;
  sm[O_T+(t&31)+32*((t>>5)+8)]=vv1;
  __syncthreads();

  // apply W_o2: HE / CS
  #pragma unroll
  for(int r2=0;r2<2;r2++){
    int q=t+(r2<<8),hid=q>>4,hd=(q>>2)&3,m=q&3;
    float vv=0;
    #pragma unroll 8
    for(int o=0;o<32;o++)
      vv=fmaf(sm[O_WM+o*32+hid],sm[O_T+((o>>2)*4+hd)+32*(((o&3)<<2)+m)],vv);
    float b2=sm[O_B2+hid];int c=hid*4+hd;
    if(m==0)sm[O_HE+c]=vv+b2;
    else sm[O_CS+c*3+m-1]=(vv+b2*sm[O_U+hd*3+m-1])*(1.f/512.f);
  }
  __syncthreads();

  // epilogue
  if(t<128){
    float a0=sm[O_CS+t*3],a1=sm[O_CS+t*3+1],a2=sm[O_CS+t*3+2];
    sm[O_HCI+t]=a0*a0+a1*a1+a2*a2;
  }
  __syncthreads();
  gmv(&sm[O_HCI],128,W_pn1,b_pn1,&sm[O_T1],t);
  gmv(&sm[O_T1],32,W_pn2,b_pn2,&sm[O_T2],t);
  if(t<192)sm[O_T3-192+t>=0?0:0],void();
  if(t<192){
    float val=(t<32)?sm[O_HI+t]:(t<160)?sm[O_HE+t-32]:sm[O_T2+t-160];
    sm[O_HCI+64+t]=val;  // reuse: input vec (192) at O_HCI+64.. wait HCI used; use O_PT+1280
  }
  __syncthreads();
  {
    float* inv=&sm[O_HCI+64];
    gmv(inv,192,W_n1,b_n1,&sm[O_T1],t);
  }
  if(t<128){
    int oh=t>>2,pr=t&3;float vv=0;
    for(int ii=pr*8;ii<pr*8+8;ii++)vv=fmaf(sm[O_T1+ii],__ldg(W_n2+ii*32+oh),vv);
    vv+=__shfl_xor_sync(~0u,vv,1);vv+=__shfl_xor_sync(~0u,vv,2);
    if(pr==0){
      float hv=sm[O_HI+oh]+silu(vv+__ldg(b_n2+oh));
      sm[O_T2+oh]=hv;
      out[(b*NN+i)*32+oh]=hv;
    }
  }
  __syncthreads();
  gmv(&sm[O_T2],32,W_v1,b_v1,&sm[O_T3],t);
  if(t<32){
    float g=sm[O_T3+t]*__ldg(W_v2+t);
    for(int s2=16;s2;s2>>=1)g+=__shfl_xor_sync(~0u,g,s2);
    if(t==0)sm[O_SC]=g;
  }
  if(t>=32&&t<128){
    int d=(t>>5)-1,ln=t&31;float vv=0;
    for(int r2=0;r2<4;r2++){int c=ln+(r2<<5);vv=fmaf(sm[O_CS+c*3+d],__ldg(W_vm+c),vv);}
    for(int s2=16;s2;s2>>=1)vv+=__shfl_xor_sync(~0u,vv,s2);
    if(ln==0)sm[O_SC+1+d]=vv;
  }
  __syncthreads();
  if(t<3){
    float vn=sm[O_SC]*sm[O_VI+t]+sm[O_SC+1+t];
    out[32768+(b*NN+i)*3+t]=sm[O_XI+t]+vn;
    out[35840+(b*NN+i)*3+t]=vn;
  }
}

extern "C" void kernel_launch(void* const* d_in,const int* in_sizes,int n_in,
                              void* d_out,int out_size){
  const float *h=(const float*)d_in[0],*x=(const float*)d_in[1],*v=(const float*)d_in[2],
    *means=(const float*)d_in[3],*betas=(const float*)d_in[4],
    *W_in=(const float*)d_in[5],*b_in=(const float*)d_in[6],
    *W_o1=(const float*)d_in[7],*b_o1=(const float*)d_in[8],
    *W_o2=(const float*)d_in[9],*b_o2=(const float*)d_in[10],
    *W_sem=(const float*)d_in[11],*b_sem=(const float*)d_in[12],
    *W_pn1=(const float*)d_in[13],*b_pn1=(const float*)d_in[14],
    *W_pn2=(const float*)d_in[15],*b_pn2=(const float*)d_in[16],
    *W_n1=(const float*)d_in[17],*b_n1=(const float*)d_in[18],
    *W_n2=(const float*)d_in[19],*b_n2=(const float*)d_in[20],
    *W_v1=(const float*)d_in[21],*b_v1=(const float*)d_in[22],
    *W_v2=(const float*)d_in[23],*W_vm=(const float*)d_in[24],
    *log_gamma=(const float*)d_in[25];
  float* out=(float*)d_out;
  cudaFuncSetAttribute(sake_main,cudaFuncAttributeMaxDynamicSharedMemorySize,SMF*4);
  pre_node<<<1024,128>>>(h,W_in,b_in,W_o1);
  pre_wos<<<1,132>>>(W_o2,W_sem,b_o2,b_sem);
  sake_main<<<1024,256,SMF*4>>>(h,x,v,means,betas,W_o1,b_o1,W_o2,b_o2,
    W_pn1,b_pn1,W_pn2,b_pn2,W_n1,b_n1,W_n2,b_n2,W_v1,b_v1,W_v2,W_vm,log_gamma,out);
}

// round 5
// speedup vs baseline: 1.4397x; 1.3987x over previous
#include <cuda_runtime.h>
#include <cuda_fp16.h>
#include <math.h>
#define NN 512
#define KK 50

__device__ float g_a[2*KK*NN], g_c[2*NN*KK], g_oa[2*32*NN], g_ob[2*NN*32];
__device__ float g_wos[128], g_bos[4];
__device__ __half g_s[(size_t)2*NN*NN*32];
__device__ float4 g_lg[2*NN*NN];
__device__ float4 g_geo[2*NN*NN];

__device__ __forceinline__ float silu(float v){return v/(1.f+__expf(-v));}
__device__ __forceinline__ unsigned long long pk(float a,float b){
  unsigned long long r;asm("mov.b64 %0,{%1,%2};":"=l"(r):"f"(a),"f"(b));return r;}
__device__ __forceinline__ void upk(unsigned long long p,float&a,float&b){
  asm("mov.b64 {%0,%1},%2;":"=f"(a),"=f"(b):"l"(p));}
__device__ __forceinline__ void fma2(unsigned long long&d,unsigned long long a,unsigned long long b){
  asm("fma.rn.f32x2 %0,%1,%2,%0;":"+l"(d):"l"(a),"l"(b));}
__device__ __forceinline__ void lds2(unsigned a,unsigned long long&x,unsigned long long&y){
  asm("ld.shared.v2.b64 {%0,%1},[%2];":"=l"(x),"=l"(y):"r"(a));}

__global__ void pre_wos(const float* __restrict__ W_o2,const float* __restrict__ W_sem,
                        const float* __restrict__ b_o2,const float* __restrict__ b_sem){
  int t=threadIdx.x;
  if(t<128){int o=t>>2,hd=t&3;float a=0;
    for(int m=0;m<32;m++)a=fmaf(W_o2[o*32+m],W_sem[m*4+hd],a);
    g_wos[t]=a;
  }else if(t<132){int hd=t-128;float a=b_sem[hd];
    for(int m=0;m<32;m++)a=fmaf(b_o2[m],W_sem[m*4+hd],a);
    g_bos[hd]=a;}
}

__global__ void pre_node(const float* __restrict__ h,const float* __restrict__ W_in,
                         const float* __restrict__ b_in,const float* __restrict__ W_o1){
  int bn=blockIdx.x,b=bn>>9,n=bn&(NN-1),t=threadIdx.x;
  __shared__ float hr[32];
  if(t<32)hr[t]=h[bn*32+t];
  __syncthreads();
  if(t<KK){
    float a=0,c=b_in[t];
    for(int f=0;f<32;f++){a=fmaf(hr[f],W_in[f*KK+t],a);c=fmaf(hr[f],W_in[(32+f)*KK+t],c);}
    g_a[((b*KK+t)<<9)+n]=a; g_c[bn*KK+t]=c;
  }else if(t>=64&&t<96){
    int q=t-64;float a=0;
    for(int f=0;f<32;f++)a=fmaf(hr[f],W_o1[f*32+q],a);
    g_oa[((b*32+q)<<9)+n]=a;
  }else if(t>=96&&t<128){
    int q=t-96;float a=0;
    for(int f=0;f<32;f++)a=fmaf(hr[f],W_o1[(32+f)*32+q],a);
    g_ob[(bn<<5)+q]=a;
  }
}

// K1: one pair per thread. sw: WM 0..1631, MBC 1632, WOS 1832, B1 1960, OB 1992, BOS 2024, XI 2028
__global__ __launch_bounds__(256,4) void k1(
  const float* __restrict__ x,const float* __restrict__ means,const float* __restrict__ betas,
  const float* __restrict__ W_o1,const float* __restrict__ b_o1){
  __shared__ float sw[2048];
  const int bi=blockIdx.x,b=bi>>10,r=bi&1023,i=r>>1,t=threadIdx.x;
  const int j=((bi&1)<<8)+t;
  const unsigned su=(unsigned)__cvta_generic_to_shared(sw);
  for(int q=t;q<1632;q+=256)sw[q]=W_o1[64*32+q];
  if(t<KK)*(float4*)&sw[1632+t*4]=make_float4(means[t],betas[t],g_c[(b*NN+i)*KK+t],0.f);
  if(t>=64&&t<192)sw[1832+t-64]=g_wos[t-64];
  if(t>=192&&t<224)sw[1960+t-192]=b_o1[t-192];
  if(t>=224)sw[1992+t-224]=g_ob[((b*NN+i)<<5)+t-224];
  if(t<4)sw[2024+t]=g_bos[t];
  if(t>=4&&t<7)sw[2028+t-4]=x[(b*NN+i)*3+t-4];
  __syncthreads();
  size_t pidx=((size_t)(b*NN+i)<<9)+j;
  const float* xj=x+(size_t)((b<<9)+j)*3;
  float d0=xj[0]-sw[2028],d1=xj[1]-sw[2029],d2=xj[2]-sw[2030];
  float nr=sqrtf(d0*d0+d1*d1+d2*d2+1e-5f),ri=1.f/(nr+1e-5f);
  g_geo[pidx]=make_float4(d0*ri,d1*ri,d2*ri,nr);
  float e=__expf(-nr);
  float cut=(nr<5.f)?0.5f*(__cosf(nr*0.6283185307179586f)+1.f):0.f;
  unsigned long long acc[16];
  const float* oa=g_oa+(((size_t)b*32)<<9)+j;
  #pragma unroll
  for(int q=0;q<16;q++)
    acc[q]=pk(oa[(size_t)(2*q)<<9]+sw[1992+2*q]+nr*sw[1600+2*q]+sw[1960+2*q],
              oa[(size_t)(2*q+1)<<9]+sw[1992+2*q+1]+nr*sw[1600+2*q+1]+sw[1960+2*q+1]);
  const float* ga=g_a+(((size_t)b*KK)<<9)+j;
  #pragma unroll 2
  for(int k=0;k<KK;k++){
    float4 mbc=*(float4*)&sw[1632+k*4];
    float dm=e-mbc.x;
    float w=cut*__expf(-mbc.y*dm*dm)*(ga[(size_t)k<<9]+mbc.z);
    unsigned long long wp=pk(w,w);
    unsigned wa=su+(unsigned)(k*128);
    #pragma unroll
    for(int q=0;q<8;q++){
      unsigned long long w0,w1;lds2(wa+q*16,w0,w1);
      fma2(acc[2*q],wp,w0);fma2(acc[2*q+1],wp,w1);
    }
  }
  float s[32];
  #pragma unroll
  for(int q=0;q<16;q++){float a,bb;upk(acc[q],a,bb);s[2*q]=silu(a);s[2*q+1]=silu(bb);}
  float4 L=make_float4(sw[2024],sw[2025],sw[2026],sw[2027]);
  #pragma unroll
  for(int q=0;q<32;q++){
    float4 wv=*(float4*)&sw[1832+q*4];
    L.x=fmaf(s[q],wv.x,L.x);L.y=fmaf(s[q],wv.y,L.y);
    L.z=fmaf(s[q],wv.z,L.z);L.w=fmaf(s[q],wv.w,L.w);
  }
  L.x=(L.x>0.f)?L.x:0.2f*L.x;L.y=(L.y>0.f)?L.y:0.2f*L.y;
  L.z=(L.z>0.f)?L.z:0.2f*L.z;L.w=(L.w>0.f)?L.w:0.2f*L.w;
  g_lg[pidx]=L;
  uint4* dst=(uint4*)(g_s+pidx*32);
  #pragma unroll
  for(int c=0;c<4;c++){
    uint4 u4;__half2* hp=(__half2*)&u4;
    hp[0]=__floats2half2_rn(s[c*8],s[c*8+1]);
    hp[1]=__floats2half2_rn(s[c*8+2],s[c*8+3]);
    hp[2]=__floats2half2_rn(s[c*8+4],s[c*8+5]);
    hp[3]=__floats2half2_rn(s[c*8+6],s[c*8+7]);
    dst[c]=u4;
  }
}

// K2 smem offsets
#define P_CW 0
#define P_SH 4096
#define P_PT 12288
#define P_T  P_PT
#define P_HE (P_PT+512)
#define P_CS (P_PT+640)
#define P_HCI (P_PT+1024)
#define P_IN (P_PT+1152)
#define P_T1 (P_PT+1344)
#define P_T2 (P_PT+1376)
#define P_T3 (P_PT+1408)
#define P_SC (P_PT+1440)
#define P_WO2 16384
#define P_B2 17408
#define P_U  17440
#define P_RD 17456
#define P_HI 17488
#define P_GM 17520
#define P_XI 17524
#define P_VI 17528
#define SMF2 17536

__device__ __forceinline__ void bred4(float* v,int mx,float* sm){
  for(int s2=16;s2;s2>>=1)
    for(int hd=0;hd<4;hd++){float o=__shfl_xor_sync(~0u,v[hd],s2);v[hd]=mx?fmaxf(v[hd],o):v[hd]+o;}
  __syncthreads();
  if((threadIdx.x&31)==0)for(int hd=0;hd<4;hd++)sm[P_RD+(threadIdx.x>>5)*4+hd]=v[hd];
  __syncthreads();
  for(int hd=0;hd<4;hd++){float r=sm[P_RD+hd];
    for(int w=1;w<8;w++){float o=sm[P_RD+w*4+hd];r=mx?fmaxf(r,o):r+o;}v[hd]=r;}
  __syncthreads();
}

__device__ __forceinline__ void gmv(const float* in,int n,const float* W,const float* bb,float* o,int t){
  if(t<128){
    int oh=t>>2,pr=t&3,ch=n>>2;float v=0;
    for(int ii=pr*ch;ii<pr*ch+ch;ii++)v=fmaf(in[ii],__ldg(W+ii*32+oh),v);
    v+=__shfl_xor_sync(~0u,v,1);v+=__shfl_xor_sync(~0u,v,2);
    if(pr==0)o[oh]=silu(v+__ldg(bb+oh));
  }
  __syncthreads();
}

__global__ __launch_bounds__(256,3) void k2(
  const float* __restrict__ h,const float* __restrict__ x,const float* __restrict__ v,
  const float* __restrict__ W_o2,const float* __restrict__ b_o2,
  const float* __restrict__ W_pn1,const float* __restrict__ b_pn1,
  const float* __restrict__ W_pn2,const float* __restrict__ b_pn2,
  const float* __restrict__ W_n1,const float* __restrict__ b_n1,
  const float* __restrict__ W_n2,const float* __restrict__ b_n2,
  const float* __restrict__ W_v1,const float* __restrict__ b_v1,
  const float* __restrict__ W_v2,const float* __restrict__ W_vm,
  const float* __restrict__ log_gamma,float* __restrict__ out){
  extern __shared__ float sm[];
  const int b=blockIdx.x>>9,i=blockIdx.x&(NN-1),t=threadIdx.x;
  const size_t base=((size_t)(b*NN+i))<<9;
  for(int q=t;q<1024;q+=256)sm[P_WO2+q]=W_o2[q];
  if(t<32){sm[P_B2+t]=b_o2[t];sm[P_HI+t]=h[(b*NN+i)*32+t];}
  if(t>=32&&t<36)sm[P_GM+t-32]=__expf(log_gamma[t-32]);
  if(t>=36&&t<39){sm[P_XI+t-36]=x[(b*NN+i)*3+t-36];sm[P_VI+t-36]=v[(b*NN+i)*3+t-36];}
  const uint4* spp=(const uint4*)(g_s+base*32);
  for(int q=t;q<2048;q+=256)((uint4*)(sm+P_SH+((q>>2)<<4)))[q&3]=spp[q];
  int j0=t,j1=t+256;
  float4 ge0=g_geo[base+j0],ge1=g_geo[base+j1];
  *(float4*)&sm[P_CW+j0*8+4]=make_float4(ge0.x,ge0.y,ge0.z,0.f);
  *(float4*)&sm[P_CW+j1*8+4]=make_float4(ge1.x,ge1.y,ge1.z,0.f);
  float4 q0=g_lg[base+j0],q1=g_lg[base+j1];
  __syncthreads();
  float nr0=ge0.w,nr1=ge1.w;
  float mk0=(j0==i)?1e5f:0.f,mk1=(j1==i)?1e5f:0.f;
  float s0[4]={q0.x-mk0,q0.y-mk0,q0.z-mk0,q0.w-mk0};
  float s1[4]={q1.x-mk1,q1.y-mk1,q1.z-mk1,q1.w-mk1};
  float e0[4],e1[4],r[4],c0[4],c1[4];
  for(int hd=0;hd<4;hd++){float g=sm[P_GM+hd];
    e0[hd]=-(nr0+mk0)*g;e1[hd]=-(nr1+mk1)*g;r[hd]=fmaxf(e0[hd],e1[hd]);}
  bred4(r,1,sm);
  for(int hd=0;hd<4;hd++){e0[hd]=__expf(e0[hd]-r[hd]);e1[hd]=__expf(e1[hd]-r[hd]);r[hd]=e0[hd]+e1[hd];}
  bred4(r,0,sm);
  for(int hd=0;hd<4;hd++){float iv=1.f/r[hd];e0[hd]*=iv;e1[hd]*=iv;r[hd]=fmaxf(s0[hd],s1[hd]);}
  bred4(r,1,sm);
  for(int hd=0;hd<4;hd++){s0[hd]=__expf(s0[hd]-r[hd]);s1[hd]=__expf(s1[hd]-r[hd]);r[hd]=s0[hd]+s1[hd];}
  bred4(r,0,sm);
  for(int hd=0;hd<4;hd++){float iv=1.f/r[hd];s0[hd]*=iv;s1[hd]*=iv;}
  for(int hd=0;hd<4;hd++){c0[hd]=__expf(e0[hd]*s0[hd]);c1[hd]=__expf(e1[hd]*s1[hd]);r[hd]=c0[hd]+c1[hd];}
  bred4(r,0,sm);
  for(int hd=0;hd<4;hd++){float iv=1.f/r[hd];c0[hd]*=iv;c1[hd]*=iv;}
  *(float4*)&sm[P_CW+j0*8]=make_float4(c0[0],c0[1],c0[2],c0[3]);
  *(float4*)&sm[P_CW+j1*8]=make_float4(c1[0],c1[1],c1[2],c1[3]);
  float ua[3]={ge0.x,ge0.y,ge0.z},ub[3]={ge1.x,ge1.y,ge1.z};
  for(int d=0;d<3;d++){
    for(int hd=0;hd<4;hd++)r[hd]=c0[hd]*ua[d]+c1[hd]*ub[d];
    bred4(r,0,sm);
    if(t==0)for(int hd=0;hd<4;hd++)sm[P_U+hd*3+d]=r[hd];
  }
  __syncthreads();
  // phase C
  {
    int lane=t&31,slice=t>>5,og=lane>>2,hd=lane&3;
    unsigned long long ac[4][2];
    #pragma unroll
    for(int c=0;c<4;c++){ac[c][0]=0ull;ac[c][1]=0ull;}
    int jb=slice<<6;
    for(int jj=0;jj<64;jj++){
      int j=jb+jj;
      uint2 sp=*(uint2*)&sm[P_SH+j*16+og*2];
      float2 fA=__half22float2(*(__half2*)&sp.x),fB=__half22float2(*(__half2*)&sp.y);
      float cb=sm[P_CW+j*8+hd];
      float4 un=*(float4*)&sm[P_CW+j*8+4];
      unsigned long long w01=pk(1.f,un.x),w23=pk(un.y,un.z),p;
      p=pk(fA.x*cb,fA.x*cb);fma2(ac[0][0],p,w01);fma2(ac[0][1],p,w23);
      p=pk(fA.y*cb,fA.y*cb);fma2(ac[1][0],p,w01);fma2(ac[1][1],p,w23);
      p=pk(fB.x*cb,fB.x*cb);fma2(ac[2][0],p,w01);fma2(ac[2][1],p,w23);
      p=pk(fB.y*cb,fB.y*cb);fma2(ac[3][0],p,w01);fma2(ac[3][1],p,w23);
    }
    #pragma unroll
    for(int c=0;c<4;c++){
      float v0,v1,v2,v3;upk(ac[c][0],v0,v1);upk(ac[c][1],v2,v3);
      int ix=c*4;
      sm[P_PT+lane+32*((ix+0)*8+slice)]=v0;
      sm[P_PT+lane+32*((ix+1)*8+slice)]=v1;
      sm[P_PT+lane+32*((ix+2)*8+slice)]=v2;
      sm[P_PT+lane+32*((ix+3)*8+slice)]=v3;
    }
  }
  __syncthreads();
  float vv0=0,vv1=0;
  {
    int combo=t&31,i0=t>>5,i1=(t>>5)+8;
    #pragma unroll
    for(int s2=0;s2<8;s2++){
      vv0+=sm[P_PT+combo+32*(i0*8+s2)];
      vv1+=sm[P_PT+combo+32*(i1*8+s2)];
    }
  }
  __syncthreads();
  sm[P_T+(t&31)+32*(t>>5)]=vv0;
  sm[P_T+(t&31)+32*((t>>5)+8)]=vv1;
  __syncthreads();
  #pragma unroll
  for(int r2=0;r2<2;r2++){
    int q=t+(r2<<8),hid=q>>4,hd=(q>>2)&3,m=q&3;
    float vv=0;
    #pragma unroll 8
    for(int o=0;o<32;o++)
      vv=fmaf(sm[P_WO2+o*32+hid],sm[P_T+((o>>2)*4+hd)+32*(((o&3)<<2)+m)],vv);
    float b2=sm[P_B2+hid];int c=hid*4+hd;
    if(m==0)sm[P_HE+c]=vv+b2;
    else sm[P_CS+c*3+m-1]=(vv+b2*sm[P_U+hd*3+m-1])*(1.f/512.f);
  }
  __syncthreads();
  if(t<128){
    float a0=sm[P_CS+t*3],a1=sm[P_CS+t*3+1],a2=sm[P_CS+t*3+2];
    sm[P_HCI+t]=a0*a0+a1*a1+a2*a2;
  }
  __syncthreads();
  gmv(&sm[P_HCI],128,W_pn1,b_pn1,&sm[P_T1],t);
  gmv(&sm[P_T1],32,W_pn2,b_pn2,&sm[P_T2],t);
  if(t<192)sm[P_IN+t]=(t<32)?sm[P_HI+t]:(t<160)?sm[P_HE+t-32]:sm[P_T2+t-160];
  __syncthreads();
  gmv(&sm[P_IN],192,W_n1,b_n1,&sm[P_T1],t);
  if(t<128){
    int oh=t>>2,pr=t&3;float vv=0;
    for(int ii=pr*8;ii<pr*8+8;ii++)vv=fmaf(sm[P_T1+ii],__ldg(W_n2+ii*32+oh),vv);
    vv+=__shfl_xor_sync(~0u,vv,1);vv+=__shfl_xor_sync(~0u,vv,2);
    if(pr==0){
      float hv=sm[P_HI+oh]+silu(vv+__ldg(b_n2+oh));
      sm[P_T2+oh]=hv;
      out[(b*NN+i)*32+oh]=hv;
    }
  }
  __syncthreads();
  gmv(&sm[P_T2],32,W_v1,b_v1,&sm[P_T3],t);
  if(t<32){
    float g=sm[P_T3+t]*__ldg(W_v2+t);
    for(int s2=16;s2;s2>>=1)g+=__shfl_xor_sync(~0u,g,s2);
    if(t==0)sm[P_SC]=g;
  }
  if(t>=32&&t<128){
    int d=(t>>5)-1,ln=t&31;float vv=0;
    for(int r2=0;r2<4;r2++){int c=ln+(r2<<5);vv=fmaf(sm[P_CS+c*3+d],__ldg(W_vm+c),vv);}
    for(int s2=16;s2;s2>>=1)vv+=__shfl_xor_sync(~0u,vv,s2);
    if(ln==0)sm[P_SC+1+d]=vv;
  }
  __syncthreads();
  if(t<3){
    float vn=sm[P_SC]*sm[P_VI+t]+sm[P_SC+1+t];
    out[32768+(b*NN+i)*3+t]=sm[P_XI+t]+vn;
    out[35840+(b*NN+i)*3+t]=vn;
  }
}

extern "C" void kernel_launch(void* const* d_in,const int* in_sizes,int n_in,
                              void* d_out,int out_size){
  const float *h=(const float*)d_in[0],*x=(const float*)d_in[1],*v=(const float*)d_in[2],
    *means=(const float*)d_in[3],*betas=(const float*)d_in[4],
    *W_in=(const float*)d_in[5],*b_in=(const float*)d_in[6],
    *W_o1=(const float*)d_in[7],*b_o1=(const float*)d_in[8],
    *W_o2=(const float*)d_in[9],*b_o2=(const float*)d_in[10],
    *W_sem=(const float*)d_in[11],*b_sem=(const float*)d_in[12],
    *W_pn1=(const float*)d_in[13],*b_pn1=(const float*)d_in[14],
    *W_pn2=(const float*)d_in[15],*b_pn2=(const float*)d_in[16],
    *W_n1=(const float*)d_in[17],*b_n1=(const float*)d_in[18],
    *W_n2=(const float*)d_in[19],*b_n2=(const float*)d_in[20],
    *W_v1=(const float*)d_in[21],*b_v1=(const float*)d_in[22],
    *W_v2=(const float*)d_in[23],*W_vm=(const float*)d_in[24],
    *log_gamma=(const float*)d_in[25];
  float* out=(float*)d_out;
  cudaFuncSetAttribute(k2,cudaFuncAttributeMaxDynamicSharedMemorySize,SMF2*4);
  pre_node<<<1024,128>>>(h,W_in,b_in,W_o1);
  pre_wos<<<1,132>>>(W_o2,W_sem,b_o2,b_sem);
  k1<<<2048,256>>>(x,means,betas,W_o1,b_o1);
  k2<<<1024,256,SMF2*4>>>(h,x,v,W_o2,b_o2,W_pn1,b_pn1,W_pn2,b_pn2,
    W_n1,b_n1,W_n2,b_n2,W_v1,b_v1,W_v2,W_vm,log_gamma,out);
}

// round 6
// speedup vs baseline: 1.4456x; 1.0042x over previous
#include <cuda_runtime.h>
#include <cuda_fp16.h>
#include <math.h>
#define NN 512
#define KK 50

__device__ float g_a[2*KK*NN], g_c[2*NN*KK], g_oa[2*32*NN], g_ob[2*NN*32];
__device__ float g_wos[128], g_bos[4];
__device__ __half g_s[(size_t)2*NN*NN*32];
__device__ float4 g_lg[2*NN*NN];
__device__ float4 g_geo[2*NN*NN];

__device__ __forceinline__ float silu(float v){return v/(1.f+__expf(-v));}
__device__ __forceinline__ unsigned long long pk(float a,float b){
  unsigned long long r;asm("mov.b64 %0,{%1,%2};":"=l"(r):"f"(a),"f"(b));return r;}
__device__ __forceinline__ void upk(unsigned long long p,float&a,float&b){
  asm("mov.b64 {%0,%1},%2;":"=f"(a),"=f"(b):"l"(p));}
__device__ __forceinline__ void fma2(unsigned long long&d,unsigned long long a,unsigned long long b){
  asm("fma.rn.f32x2 %0,%1,%2,%0;":"+l"(d):"l"(a),"l"(b));}
__device__ __forceinline__ void lds2(unsigned a,unsigned long long&x,unsigned long long&y){
  asm("ld.shared.v2.b64 {%0,%1},[%2];":"=l"(x),"=l"(y):"r"(a));}

__global__ void pre_wos(const float* __restrict__ W_o2,const float* __restrict__ W_sem,
                        const float* __restrict__ b_o2,const float* __restrict__ b_sem){
  int t=threadIdx.x;
  if(t<128){int o=t>>2,hd=t&3;float a=0;
    for(int m=0;m<32;m++)a=fmaf(W_o2[o*32+m],W_sem[m*4+hd],a);
    g_wos[t]=a;
  }else if(t<132){int hd=t-128;float a=b_sem[hd];
    for(int m=0;m<32;m++)a=fmaf(b_o2[m],W_sem[m*4+hd],a);
    g_bos[hd]=a;}
}

__global__ void pre_node(const float* __restrict__ h,const float* __restrict__ W_in,
                         const float* __restrict__ b_in,const float* __restrict__ W_o1){
  int bn=blockIdx.x,b=bn>>9,n=bn&(NN-1),t=threadIdx.x;
  __shared__ float hr[32];
  if(t<32)hr[t]=h[bn*32+t];
  __syncthreads();
  if(t<KK){
    float a=0,c=b_in[t];
    for(int f=0;f<32;f++){a=fmaf(hr[f],W_in[f*KK+t],a);c=fmaf(hr[f],W_in[(32+f)*KK+t],c);}
    g_a[((b*KK+t)<<9)+n]=a; g_c[bn*KK+t]=c;
  }else if(t>=64&&t<96){
    int q=t-64;float a=0;
    for(int f=0;f<32;f++)a=fmaf(hr[f],W_o1[f*32+q],a);
    g_oa[((b*32+q)<<9)+n]=a;
  }else if(t>=96&&t<128){
    int q=t-96;float a=0;
    for(int f=0;f<32;f++)a=fmaf(hr[f],W_o1[(32+f)*32+q],a);
    g_ob[(bn<<5)+q]=a;
  }
}

// K1: one pair per thread
__global__ __launch_bounds__(256,4) void k1(
  const float* __restrict__ x,const float* __restrict__ means,const float* __restrict__ betas,
  const float* __restrict__ W_o1,const float* __restrict__ b_o1){
  __shared__ float sw[2048];
  const int bi=blockIdx.x,b=bi>>10,r=bi&1023,i=r>>1,t=threadIdx.x;
  const int j=((bi&1)<<8)+t;
  const unsigned su=(unsigned)__cvta_generic_to_shared(sw);
  for(int q=t;q<1632;q+=256)sw[q]=W_o1[64*32+q];
  if(t<KK)*(float4*)&sw[1632+t*4]=make_float4(means[t],betas[t],g_c[(b*NN+i)*KK+t],0.f);
  if(t>=64&&t<192)sw[1832+t-64]=g_wos[t-64];
  if(t>=192&&t<224)sw[1960+t-192]=b_o1[t-192];
  if(t>=224)sw[1992+t-224]=g_ob[((b*NN+i)<<5)+t-224];
  if(t<4)sw[2024+t]=g_bos[t];
  if(t>=4&&t<7)sw[2028+t-4]=x[(b*NN+i)*3+t-4];
  __syncthreads();
  size_t pidx=((size_t)(b*NN+i)<<9)+j;
  const float* xj=x+(size_t)((b<<9)+j)*3;
  float d0=xj[0]-sw[2028],d1=xj[1]-sw[2029],d2=xj[2]-sw[2030];
  float nr=sqrtf(d0*d0+d1*d1+d2*d2+1e-5f),ri=1.f/(nr+1e-5f);
  g_geo[pidx]=make_float4(d0*ri,d1*ri,d2*ri,nr);
  float e=__expf(-nr);
  float cut=(nr<5.f)?0.5f*(__cosf(nr*0.6283185307179586f)+1.f):0.f;
  unsigned long long acc[16];
  const float* oa=g_oa+(((size_t)b*32)<<9)+j;
  #pragma unroll
  for(int q=0;q<16;q++)
    acc[q]=pk(oa[(size_t)(2*q)<<9]+sw[1992+2*q]+nr*sw[1600+2*q]+sw[1960+2*q],
              oa[(size_t)(2*q+1)<<9]+sw[1992+2*q+1]+nr*sw[1600+2*q+1]+sw[1960+2*q+1]);
  const float* ga=g_a+(((size_t)b*KK)<<9)+j;
  #pragma unroll 2
  for(int k=0;k<KK;k++){
    float4 mbc=*(float4*)&sw[1632+k*4];
    float dm=e-mbc.x;
    float w=cut*__expf(-mbc.y*dm*dm)*(ga[(size_t)k<<9]+mbc.z);
    unsigned long long wp=pk(w,w);
    unsigned wa=su+(unsigned)(k*128);
    #pragma unroll
    for(int q=0;q<8;q++){
      unsigned long long w0,w1;lds2(wa+q*16,w0,w1);
      fma2(acc[2*q],wp,w0);fma2(acc[2*q+1],wp,w1);
    }
  }
  // in-place: silu -> sem dot -> half2 pack (no s[32] array)
  float4 L=make_float4(sw[2024],sw[2025],sw[2026],sw[2027]);
  unsigned hs[16];
  #pragma unroll
  for(int q=0;q<16;q++){
    float a,bb;upk(acc[q],a,bb);
    a=silu(a);bb=silu(bb);
    float4 wa=*(float4*)&sw[1832+(2*q)*4];
    float4 wb=*(float4*)&sw[1832+(2*q+1)*4];
    L.x=fmaf(a,wa.x,fmaf(bb,wb.x,L.x));
    L.y=fmaf(a,wa.y,fmaf(bb,wb.y,L.y));
    L.z=fmaf(a,wa.z,fmaf(bb,wb.z,L.z));
    L.w=fmaf(a,wa.w,fmaf(bb,wb.w,L.w));
    __half2 hh=__floats2half2_rn(a,bb);
    hs[q]=*(unsigned*)&hh;
  }
  L.x=(L.x>0.f)?L.x:0.2f*L.x;L.y=(L.y>0.f)?L.y:0.2f*L.y;
  L.z=(L.z>0.f)?L.z:0.2f*L.z;L.w=(L.w>0.f)?L.w:0.2f*L.w;
  g_lg[pidx]=L;
  uint4* dst=(uint4*)(g_s+pidx*32);
  #pragma unroll
  for(int c=0;c<4;c++)dst[c]=make_uint4(hs[c*4],hs[c*4+1],hs[c*4+2],hs[c*4+3]);
}

// K2 smem offsets
#define P_CW 0
#define P_SH 4096
#define P_PT 12288
#define P_T  P_PT
#define P_HE (P_PT+512)
#define P_CS (P_PT+640)
#define P_HCI (P_PT+1024)
#define P_IN (P_PT+1152)
#define P_T1 (P_PT+1344)
#define P_T2 (P_PT+1376)
#define P_T3 (P_PT+1408)
#define P_SC (P_PT+1440)
#define P_WO2 16384
#define P_B2 17408
#define P_U  17440
#define P_RD 17456   // 128 floats
#define P_HI 17584
#define P_GM 17616
#define P_XI 17620
#define P_VI 17624
#define SMF2 17632

template<int NV>
__device__ __forceinline__ void bredN(float* v,int mx,float* sm){
  #pragma unroll
  for(int s2=16;s2;s2>>=1)
    #pragma unroll
    for(int q=0;q<NV;q++){float o=__shfl_xor_sync(~0u,v[q],s2);v[q]=mx?fmaxf(v[q],o):v[q]+o;}
  __syncthreads();
  if((threadIdx.x&31)==0)
    #pragma unroll
    for(int q=0;q<NV;q++)sm[P_RD+(threadIdx.x>>5)*NV+q]=v[q];
  __syncthreads();
  #pragma unroll
  for(int q=0;q<NV;q++){float r=sm[P_RD+q];
    #pragma unroll
    for(int w=1;w<8;w++){float o=sm[P_RD+w*NV+q];r=mx?fmaxf(r,o):r+o;}v[q]=r;}
  __syncthreads();
}

template<int NI>
__device__ __forceinline__ void gmv(const float* in,const float* __restrict__ W,
                                    const float* __restrict__ bb,float* o,int t){
  if(t<128){
    int oh=t>>2,pr=t&3;
    constexpr int CH=NI/4;
    float v=0;
    #pragma unroll
    for(int q=0;q<CH;q++)v=fmaf(in[pr*CH+q],__ldg(W+(pr*CH+q)*32+oh),v);
    v+=__shfl_xor_sync(~0u,v,1);v+=__shfl_xor_sync(~0u,v,2);
    if(pr==0)o[oh]=silu(v+__ldg(bb+oh));
  }
  __syncthreads();
}

__global__ __launch_bounds__(256,3) void k2(
  const float* __restrict__ h,const float* __restrict__ x,const float* __restrict__ v,
  const float* __restrict__ W_o2,const float* __restrict__ b_o2,
  const float* __restrict__ W_pn1,const float* __restrict__ b_pn1,
  const float* __restrict__ W_pn2,const float* __restrict__ b_pn2,
  const float* __restrict__ W_n1,const float* __restrict__ b_n1,
  const float* __restrict__ W_n2,const float* __restrict__ b_n2,
  const float* __restrict__ W_v1,const float* __restrict__ b_v1,
  const float* __restrict__ W_v2,const float* __restrict__ W_vm,
  const float* __restrict__ log_gamma,float* __restrict__ out){
  extern __shared__ float sm[];
  const int b=blockIdx.x>>9,i=blockIdx.x&(NN-1),t=threadIdx.x;
  const size_t base=((size_t)(b*NN+i))<<9;
  for(int q=t;q<1024;q+=256)sm[P_WO2+q]=W_o2[q];
  if(t<32){sm[P_B2+t]=b_o2[t];sm[P_HI+t]=h[(b*NN+i)*32+t];}
  if(t>=32&&t<36)sm[P_GM+t-32]=__expf(log_gamma[t-32]);
  if(t>=36&&t<39){sm[P_XI+t-36]=x[(b*NN+i)*3+t-36];sm[P_VI+t-36]=v[(b*NN+i)*3+t-36];}
  const uint4* spp=(const uint4*)(g_s+base*32);
  for(int q=t;q<2048;q+=256)((uint4*)(sm+P_SH+((q>>2)<<4)))[q&3]=spp[q];
  int j0=t,j1=t+256;
  float4 ge0=g_geo[base+j0],ge1=g_geo[base+j1];
  *(float4*)&sm[P_CW+j0*8+4]=make_float4(ge0.x,ge0.y,ge0.z,0.f);
  *(float4*)&sm[P_CW+j1*8+4]=make_float4(ge1.x,ge1.y,ge1.z,0.f);
  float4 q0=g_lg[base+j0],q1=g_lg[base+j1];
  __syncthreads();
  float nr0=ge0.w,nr1=ge1.w;
  float mk0=(j0==i)?1e5f:0.f,mk1=(j1==i)?1e5f:0.f;
  float s0[4]={q0.x-mk0,q0.y-mk0,q0.z-mk0,q0.w-mk0};
  float s1[4]={q1.x-mk1,q1.y-mk1,q1.z-mk1,q1.w-mk1};
  float e0[4],e1[4],r[4];
  // eucl: logits <=0, no max-subtract needed (self -> exp(-2e4*g)=0)
  #pragma unroll
  for(int hd=0;hd<4;hd++){float g=sm[P_GM+hd];
    e0[hd]=__expf(-(nr0+mk0)*g);e1[hd]=__expf(-(nr1+mk1)*g);r[hd]=e0[hd]+e1[hd];}
  bredN<4>(r,0,sm);
  #pragma unroll
  for(int hd=0;hd<4;hd++){float iv=1.f/r[hd];e0[hd]*=iv;e1[hd]*=iv;r[hd]=fmaxf(s0[hd],s1[hd]);}
  bredN<4>(r,1,sm);
  #pragma unroll
  for(int hd=0;hd<4;hd++){s0[hd]=__expf(s0[hd]-r[hd]);s1[hd]=__expf(s1[hd]-r[hd]);r[hd]=s0[hd]+s1[hd];}
  bredN<4>(r,0,sm);
  // comb: fuse denominator + U numerators (16-wide)
  float R[16];
  #pragma unroll
  for(int hd=0;hd<4;hd++){
    float iv=1.f/r[hd];s0[hd]*=iv;s1[hd]*=iv;
    float c0=__expf(e0[hd]*s0[hd]),c1=__expf(e1[hd]*s1[hd]);
    e0[hd]=c0;e1[hd]=c1;       // reuse as comb-exp
    R[hd]=c0+c1;
    R[4+hd*3+0]=c0*ge0.x+c1*ge1.x;
    R[4+hd*3+1]=c0*ge0.y+c1*ge1.y;
    R[4+hd*3+2]=c0*ge0.z+c1*ge1.z;
  }
  bredN<16>(R,0,sm);
  #pragma unroll
  for(int hd=0;hd<4;hd++){float iv=1.f/R[hd];e0[hd]*=iv;e1[hd]*=iv;}
  *(float4*)&sm[P_CW+j0*8]=make_float4(e0[0],e0[1],e0[2],e0[3]);
  *(float4*)&sm[P_CW+j1*8]=make_float4(e1[0],e1[1],e1[2],e1[3]);
  if(t<12){int hd=t/3,d=t%3;sm[P_U+hd*3+d]=R[4+hd*3+d]/R[hd];}
  __syncthreads();
  // phase C
  {
    int lane=t&31,slice=t>>5,og=lane>>2,hd=lane&3;
    unsigned long long ac[4][2];
    #pragma unroll
    for(int c=0;c<4;c++){ac[c][0]=0ull;ac[c][1]=0ull;}
    int jb=slice<<6;
    for(int jj=0;jj<64;jj++){
      int j=jb+jj;
      uint2 sp=*(uint2*)&sm[P_SH+j*16+og*2];
      float2 fA=__half22float2(*(__half2*)&sp.x),fB=__half22float2(*(__half2*)&sp.y);
      float cb=sm[P_CW+j*8+hd];
      float4 un=*(float4*)&sm[P_CW+j*8+4];
      unsigned long long w01=pk(1.f,un.x),w23=pk(un.y,un.z),p;
      p=pk(fA.x*cb,fA.x*cb);fma2(ac[0][0],p,w01);fma2(ac[0][1],p,w23);
      p=pk(fA.y*cb,fA.y*cb);fma2(ac[1][0],p,w01);fma2(ac[1][1],p,w23);
      p=pk(fB.x*cb,fB.x*cb);fma2(ac[2][0],p,w01);fma2(ac[2][1],p,w23);
      p=pk(fB.y*cb,fB.y*cb);fma2(ac[3][0],p,w01);fma2(ac[3][1],p,w23);
    }
    #pragma unroll
    for(int c=0;c<4;c++){
      float v0,v1,v2,v3;upk(ac[c][0],v0,v1);upk(ac[c][1],v2,v3);
      int ix=c*4;
      sm[P_PT+lane+32*((ix+0)*8+slice)]=v0;
      sm[P_PT+lane+32*((ix+1)*8+slice)]=v1;
      sm[P_PT+lane+32*((ix+2)*8+slice)]=v2;
      sm[P_PT+lane+32*((ix+3)*8+slice)]=v3;
    }
  }
  __syncthreads();
  float vv0=0,vv1=0;
  {
    int combo=t&31,i0=t>>5,i1=(t>>5)+8;
    #pragma unroll
    for(int s2=0;s2<8;s2++){
      vv0+=sm[P_PT+combo+32*(i0*8+s2)];
      vv1+=sm[P_PT+combo+32*(i1*8+s2)];
    }
  }
  __syncthreads();
  sm[P_T+(t&31)+32*(t>>5)]=vv0;
  sm[P_T+(t&31)+32*((t>>5)+8)]=vv1;
  __syncthreads();
  #pragma unroll
  for(int r2=0;r2<2;r2++){
    int q=t+(r2<<8),hid=q>>4,hd=(q>>2)&3,m=q&3;
    float vv=0;
    #pragma unroll 8
    for(int o=0;o<32;o++)
      vv=fmaf(sm[P_WO2+o*32+hid],sm[P_T+((o>>2)*4+hd)+32*(((o&3)<<2)+m)],vv);
    float b2=sm[P_B2+hid];int c=hid*4+hd;
    if(m==0)sm[P_HE+c]=vv+b2;
    else sm[P_CS+c*3+m-1]=(vv+b2*sm[P_U+hd*3+m-1])*(1.f/512.f);
  }
  __syncthreads();
  if(t<128){
    float a0=sm[P_CS+t*3],a1=sm[P_CS+t*3+1],a2=sm[P_CS+t*3+2];
    sm[P_HCI+t]=a0*a0+a1*a1+a2*a2;
  }
  __syncthreads();
  gmv<128>(&sm[P_HCI],W_pn1,b_pn1,&sm[P_T1],t);
  gmv<32>(&sm[P_T1],W_pn2,b_pn2,&sm[P_T2],t);
  if(t<192)sm[P_IN+t]=(t<32)?sm[P_HI+t]:(t<160)?sm[P_HE+t-32]:sm[P_T2+t-160];
  __syncthreads();
  gmv<192>(&sm[P_IN],W_n1,b_n1,&sm[P_T1],t);
  if(t<128){
    int oh=t>>2,pr=t&3;float vv=0;
    #pragma unroll
    for(int q=0;q<8;q++)vv=fmaf(sm[P_T1+pr*8+q],__ldg(W_n2+(pr*8+q)*32+oh),vv);
    vv+=__shfl_xor_sync(~0u,vv,1);vv+=__shfl_xor_sync(~0u,vv,2);
    if(pr==0){
      float hv=sm[P_HI+oh]+silu(vv+__ldg(b_n2+oh));
      sm[P_T2+oh]=hv;
      out[(b*NN+i)*32+oh]=hv;
    }
  }
  __syncthreads();
  gmv<32>(&sm[P_T2],W_v1,b_v1,&sm[P_T3],t);
  if(t<32){
    float g=sm[P_T3+t]*__ldg(W_v2+t);
    #pragma unroll
    for(int s2=16;s2;s2>>=1)g+=__shfl_xor_sync(~0u,g,s2);
    if(t==0)sm[P_SC]=g;
  }
  if(t>=32&&t<128){
    int d=(t>>5)-1,ln=t&31;float vv=0;
    #pragma unroll
    for(int r2=0;r2<4;r2++){int c=ln+(r2<<5);vv=fmaf(sm[P_CS+c*3+d],__ldg(W_vm+c),vv);}
    #pragma unroll
    for(int s2=16;s2;s2>>=1)vv+=__shfl_xor_sync(~0u,vv,s2);
    if(ln==0)sm[P_SC+1+d]=vv;
  }
  __syncthreads();
  if(t<3){
    float vn=sm[P_SC]*sm[P_VI+t]+sm[P_SC+1+t];
    out[32768+(b*NN+i)*3+t]=sm[P_XI+t]+vn;
    out[35840+(b*NN+i)*3+t]=vn;
  }
}

extern "C" void kernel_launch(void* const* d_in,const int* in_sizes,int n_in,
                              void* d_out,int out_size){
  const float *h=(const float*)d_in[0],*x=(const float*)d_in[1],*v=(const float*)d_in[2],
    *means=(const float*)d_in[3],*betas=(const float*)d_in[4],
    *W_in=(const float*)d_in[5],*b_in=(const float*)d_in[6],
    *W_o1=(const float*)d_in[7],*b_o1=(const float*)d_in[8],
    *W_o2=(const float*)d_in[9],*b_o2=(const float*)d_in[10],
    *W_sem=(const float*)d_in[11],*b_sem=(const float*)d_in[12],
    *W_pn1=(const float*)d_in[13],*b_pn1=(const float*)d_in[14],
    *W_pn2=(const float*)d_in[15],*b_pn2=(const float*)d_in[16],
    *W_n1=(const float*)d_in[17],*b_n1=(const float*)d_in[18],
    *W_n2=(const float*)d_in[19],*b_n2=(const float*)d_in[20],
    *W_v1=(const float*)d_in[21],*b_v1=(const float*)d_in[22],
    *W_v2=(const float*)d_in[23],*W_vm=(const float*)d_in[24],
    *log_gamma=(const float*)d_in[25];
  float* out=(float*)d_out;
  cudaFuncSetAttribute(k2,cudaFuncAttributeMaxDynamicSharedMemorySize,SMF2*4);
  pre_node<<<1024,128>>>(h,W_in,b_in,W_o1);
  pre_wos<<<1,132>>>(W_o2,W_sem,b_o2,b_sem);
  k1<<<2048,256>>>(x,means,betas,W_o1,b_o1);
  k2<<<1024,256,SMF2*4>>>(h,x,v,W_o2,b_o2,W_pn1,b_pn1,W_pn2,b_pn2,
    W_n1,b_n1,W_n2,b_n2,W_v1,b_v1,W_v2,W_vm,log_gamma,out);
}